// round 2
// baseline (speedup 1.0000x reference)
#include <cuda_runtime.h>
#include <cstdint>

#define KSZ 5
#define NBUCKETS 25
#define BATCH 8
#define CHANNELS 96
#define HEIGHT 192
#define WIDTH 192

#define TW 32          // tile width  (threads x)
#define TH 8           // tile height (threads y)
#define CH_UNROLL 4    // channels per iteration
#define HALO 2
#define TILE_H (TH + 2*HALO)   // 12
#define TILE_W (TW + 2*HALO)   // 36

__global__ __launch_bounds__(TW*TH) void csconv2d_kernel(
    const float* __restrict__ input,        // [B,C,H,W]
    const float* __restrict__ kernel_bank,  // [25,5,5]
    const int* __restrict__ buckets,        // [B,H,W] (int32: jax x64 disabled)
    float* __restrict__ output)             // [B,C,H,W]
{
    __shared__ float s_bank[NBUCKETS * KSZ * KSZ];                 // 2.5 KB
    __shared__ float s_tile[CH_UNROLL][TILE_H][TILE_W];            // 6.75 KB

    const int tx = threadIdx.x;
    const int ty = threadIdx.y;
    const int tid = ty * TW + tx;

    const int w0 = blockIdx.x * TW;
    const int h0 = blockIdx.y * TH;
    const int b  = blockIdx.z;

    const int w = w0 + tx;
    const int h = h0 + ty;

    // Stage the kernel bank into shared (625 floats).
    for (int i = tid; i < NBUCKETS * KSZ * KSZ; i += TW * TH)
        s_bank[i] = kernel_bank[i];
    __syncthreads();

    // Per-pixel bucket -> 25 weights into registers, reused for all 96 channels.
    int bkt = buckets[((long long)b * HEIGHT + h) * WIDTH + w];
    bkt = min(max(bkt, 0), NBUCKETS - 1);   // defensive clamp (no-op for valid data)
    float wk[KSZ * KSZ];
    #pragma unroll
    for (int t = 0; t < KSZ * KSZ; t++)
        wk[t] = s_bank[bkt * (KSZ * KSZ) + t];

    const float* inb  = input  + (size_t)b * CHANNELS * HEIGHT * WIDTH;
    float*       outb = output + (size_t)b * CHANNELS * HEIGHT * WIDTH;

    for (int c0 = 0; c0 < CHANNELS; c0 += CH_UNROLL) {
        __syncthreads();  // protect previous iteration's tile reads

        // Cooperative halo-tile load for CH_UNROLL channels:
        // CH_UNROLL * 12 * 36 = 1728 floats / 256 threads = 6.75 each.
        #pragma unroll
        for (int idx = tid; idx < CH_UNROLL * TILE_H * TILE_W; idx += TW * TH) {
            const int cc  = idx / (TILE_H * TILE_W);
            const int rem = idx % (TILE_H * TILE_W);
            const int r   = rem / TILE_W;
            const int col = rem % TILE_W;
            const int gh = h0 + r   - HALO;
            const int gw = w0 + col - HALO;
            float v = 0.0f;
            if ((unsigned)gh < HEIGHT && (unsigned)gw < WIDTH)
                v = inb[((size_t)(c0 + cc) * HEIGHT + gh) * WIDTH + gw];
            s_tile[cc][r][col] = v;
        }
        __syncthreads();

        float acc[CH_UNROLL];
        #pragma unroll
        for (int cc = 0; cc < CH_UNROLL; cc++) acc[cc] = 0.0f;

        #pragma unroll
        for (int i = 0; i < KSZ; i++) {
            #pragma unroll
            for (int j = 0; j < KSZ; j++) {
                const float wt = wk[i * KSZ + j];
                #pragma unroll
                for (int cc = 0; cc < CH_UNROLL; cc++)
                    acc[cc] = fmaf(s_tile[cc][ty + i][tx + j], wt, acc[cc]);
            }
        }

        #pragma unroll
        for (int cc = 0; cc < CH_UNROLL; cc++)
            outb[((size_t)(c0 + cc) * HEIGHT + h) * WIDTH + w] = acc[cc];
    }
}

extern "C" void kernel_launch(void* const* d_in, const int* in_sizes, int n_in,
                              void* d_out, int out_size)
{
    const float* input       = (const float*)d_in[0];
    const float* kernel_bank = (const float*)d_in[1];
    const int*   buckets     = (const int*)d_in[2];
    float*       output      = (float*)d_out;

    dim3 block(TW, TH, 1);
    dim3 grid(WIDTH / TW, HEIGHT / TH, BATCH);   // (6, 24, 8)
    csconv2d_kernel<<<grid, block>>>(input, kernel_bank, buckets, output);
}

// round 4
// speedup vs baseline: 1.4751x; 1.4751x over previous
#include <cuda_runtime.h>
#include <cstdint>

#define KSZ 5
#define NBUCKETS 25
#define BATCH 8
#define CHANNELS 96
#define HEIGHT 192
#define WIDTH 192

#define BTX 16            // threads x
#define BTY 16            // threads y
#define NTHREADS (BTX*BTY)
#define PX 4              // output pixels (columns) per thread
#define TILE_OW (BTX*PX)  // 64 output columns per block
#define TILE_OH BTY       // 16 output rows per block
#define HALO 2
#define TROWS (TILE_OH + 2*HALO)   // 20
#define TCOLS (TILE_OW + 2*HALO)   // 68 loaded columns
#define TSTRIDE 72                 // row stride in floats (288B, 16B-aligned)

__device__ __forceinline__ void cp_async4(uint32_t smem_dst, const void* gptr, int src_bytes) {
    asm volatile("cp.async.ca.shared.global [%0], [%1], 4, %2;\n"
                 :: "r"(smem_dst), "l"(gptr), "r"(src_bytes));
}
__device__ __forceinline__ void cp_async_commit() {
    asm volatile("cp.async.commit_group;\n" ::: "memory");
}
template <int N>
__device__ __forceinline__ void cp_async_wait() {
    asm volatile("cp.async.wait_group %0;\n" :: "n"(N) : "memory");
}

__global__ __launch_bounds__(NTHREADS, 2) void csconv2d_kernel(
    const float* __restrict__ input,        // [B,C,H,W]
    const float* __restrict__ kernel_bank,  // [25,5,5]
    const int* __restrict__ buckets,        // [B,H,W] int32
    float* __restrict__ output)             // [B,C,H,W]
{
    __shared__ __align__(16) float s_tile[2][TROWS * TSTRIDE];  // 2 * 5.76 KB, FIRST: 16B aligned
    __shared__ __align__(16) float s_bank[640];                 // 25*25=625 used, padded

    const int tx = threadIdx.x;
    const int ty = threadIdx.y;
    const int tid = ty * BTX + tx;

    const int w0 = blockIdx.x * TILE_OW;
    const int h0 = blockIdx.y * TILE_OH;
    const int b  = blockIdx.z;

    const int h = h0 + ty;            // this thread's output row
    const int wbase = w0 + PX * tx;   // first of 4 output columns

    // Stage kernel bank into shared.
    for (int i = tid; i < NBUCKETS * KSZ * KSZ; i += NTHREADS)
        s_bank[i] = kernel_bank[i];
    __syncthreads();

    // 4 buckets for this thread's 4 pixels (int4: index multiple of 4 -> 16B aligned).
    const int4 bk4 = *reinterpret_cast<const int4*>(
        &buckets[((long long)b * HEIGHT + h) * WIDTH + wbase]);
    int bkt[PX] = {bk4.x, bk4.y, bk4.z, bk4.w};
    #pragma unroll
    for (int p = 0; p < PX; p++)
        bkt[p] = min(max(bkt[p], 0), NBUCKETS - 1);

    // 100 weight registers: 25 per pixel, reused across all 96 channels.
    float wk[PX * KSZ * KSZ];
    #pragma unroll
    for (int p = 0; p < PX; p++)
        #pragma unroll
        for (int t = 0; t < KSZ * KSZ; t++)
            wk[p * 25 + t] = s_bank[bkt[p] * 25 + t];

    const float* inb  = input  + (size_t)b * CHANNELS * HEIGHT * WIDTH;
    float*       outb = output + (size_t)b * CHANNELS * HEIGHT * WIDTH;

    const uint32_t s_tile_base = (uint32_t)__cvta_generic_to_shared(&s_tile[0][0]);

    // Issue async tile load for channel c into buffer buf.
    auto issue_tile = [&](int c, int buf) {
        const float* chan = inb + (size_t)c * HEIGHT * WIDTH;
        #pragma unroll
        for (int idx = tid; idx < TROWS * TCOLS; idx += NTHREADS) {
            const int r   = idx / TCOLS;
            const int col = idx % TCOLS;
            const int gh = h0 + r - HALO;
            const int gw = w0 + col - HALO;
            const bool ok = ((unsigned)gh < HEIGHT) & ((unsigned)gw < WIDTH);
            // keep pointer in-bounds even when masked (0 bytes read)
            const float* src = chan + (ok ? ((size_t)gh * WIDTH + gw) : 0);
            const uint32_t dst = s_tile_base
                + (uint32_t)((buf * TROWS * TSTRIDE + r * TSTRIDE + col) * 4);
            cp_async4(dst, src, ok ? 4 : 0);
        }
        cp_async_commit();
    };

    issue_tile(0, 0);

    for (int c = 0; c < CHANNELS; c++) {
        const int buf = c & 1;
        if (c + 1 < CHANNELS) {
            issue_tile(c + 1, buf ^ 1);
            cp_async_wait<1>();   // channel c's group is complete
        } else {
            cp_async_wait<0>();
        }
        __syncthreads();

        float acc[PX] = {0.f, 0.f, 0.f, 0.f};

        #pragma unroll
        for (int i = 0; i < KSZ; i++) {
            const float* row = &s_tile[buf][(ty + i) * TSTRIDE + PX * tx];
            const float4 a = *reinterpret_cast<const float4*>(row);
            const float4 bq = *reinterpret_cast<const float4*>(row + 4);
            const float v[8] = {a.x, a.y, a.z, a.w, bq.x, bq.y, bq.z, bq.w};
            #pragma unroll
            for (int p = 0; p < PX; p++)
                #pragma unroll
                for (int j = 0; j < KSZ; j++)
                    acc[p] = fmaf(v[p + j], wk[p * 25 + i * KSZ + j], acc[p]);
        }

        float4 o = {acc[0], acc[1], acc[2], acc[3]};
        *reinterpret_cast<float4*>(
            &outb[((size_t)c * HEIGHT + h) * WIDTH + wbase]) = o;

        __syncthreads();  // all reads of buf done before it is refilled next iter
    }
}

extern "C" void kernel_launch(void* const* d_in, const int* in_sizes, int n_in,
                              void* d_out, int out_size)
{
    const float* input       = (const float*)d_in[0];
    const float* kernel_bank = (const float*)d_in[1];
    const int*   buckets     = (const int*)d_in[2];
    float*       output      = (float*)d_out;

    dim3 block(BTX, BTY, 1);
    dim3 grid(WIDTH / TILE_OW, HEIGHT / TILE_OH, BATCH);   // (3, 12, 8)
    csconv2d_kernel<<<grid, block>>>(input, kernel_bank, buckets, output);
}

// round 5
// speedup vs baseline: 1.7363x; 1.1771x over previous
#include <cuda_runtime.h>
#include <cstdint>

#define KSZ 5
#define NBUCKETS 25
#define BATCH 8
#define CHANNELS 96
#define HEIGHT 192
#define WIDTH 192

#define BTX 16            // threads x
#define BTY 16            // threads y
#define NTHREADS (BTX*BTY)
#define PX 4              // output pixels (columns) per thread
#define CH 2              // channels per iteration
#define TILE_OW (BTX*PX)  // 64 output columns per block
#define TILE_OH BTY       // 16 output rows per block
#define HALO 2
#define TROWS (TILE_OH + 2*HALO)   // 20
#define TCOLS (TILE_OW + 2*HALO)   // 68 loaded columns
#define TSTRIDE 72                 // row stride in floats (288B, 16B-aligned)
#define TILE_FLOATS (TROWS * TSTRIDE)

__device__ __forceinline__ void cp_async4(uint32_t smem_dst, const void* gptr, int src_bytes) {
    asm volatile("cp.async.ca.shared.global [%0], [%1], 4, %2;\n"
                 :: "r"(smem_dst), "l"(gptr), "r"(src_bytes));
}
__device__ __forceinline__ void cp_async_commit() {
    asm volatile("cp.async.commit_group;\n" ::: "memory");
}
template <int N>
__device__ __forceinline__ void cp_async_wait() {
    asm volatile("cp.async.wait_group %0;\n" :: "n"(N) : "memory");
}

__global__ __launch_bounds__(NTHREADS, 2) void csconv2d_kernel(
    const float* __restrict__ input,        // [B,C,H,W]
    const float* __restrict__ kernel_bank,  // [25,5,5]
    const int* __restrict__ buckets,        // [B,H,W] int32
    float* __restrict__ output)             // [B,C,H,W]
{
    __shared__ __align__(16) float s_tile[2][CH][TILE_FLOATS];  // 2 bufs x 2 ch x 5.76 KB
    __shared__ __align__(16) float s_bank[640];                 // 625 used

    const int tx = threadIdx.x;
    const int ty = threadIdx.y;
    const int tid = ty * BTX + tx;

    const int w0 = blockIdx.x * TILE_OW;
    const int h0 = blockIdx.y * TILE_OH;
    const int b  = blockIdx.z;

    const int h = h0 + ty;
    const int wbase = w0 + PX * tx;

    for (int i = tid; i < NBUCKETS * KSZ * KSZ; i += NTHREADS)
        s_bank[i] = kernel_bank[i];
    __syncthreads();

    const int4 bk4 = *reinterpret_cast<const int4*>(
        &buckets[((long long)b * HEIGHT + h) * WIDTH + wbase]);
    int bkt[PX] = {bk4.x, bk4.y, bk4.z, bk4.w};
    #pragma unroll
    for (int p = 0; p < PX; p++)
        bkt[p] = min(max(bkt[p], 0), NBUCKETS - 1);

    float wk[PX * 25];
    #pragma unroll
    for (int p = 0; p < PX; p++)
        #pragma unroll
        for (int t = 0; t < 25; t++)
            wk[p * 25 + t] = s_bank[bkt[p] * 25 + t];

    const float* inb  = input  + (size_t)b * CHANNELS * HEIGHT * WIDTH;
    float*       outb = output + (size_t)b * CHANNELS * HEIGHT * WIDTH;

    const uint32_t s_tile_base = (uint32_t)__cvta_generic_to_shared(&s_tile[0][0][0]);

    // Issue async tile loads for channels [c0, c0+CH) into buffer buf (one group).
    auto issue_pair = [&](int c0, int buf) {
        #pragma unroll
        for (int cc = 0; cc < CH; cc++) {
            const float* chan = inb + (size_t)(c0 + cc) * HEIGHT * WIDTH;
            #pragma unroll
            for (int idx = tid; idx < TROWS * TCOLS; idx += NTHREADS) {
                const int r   = idx / TCOLS;
                const int col = idx % TCOLS;
                const int gh = h0 + r - HALO;
                const int gw = w0 + col - HALO;
                const bool ok = ((unsigned)gh < HEIGHT) & ((unsigned)gw < WIDTH);
                const float* src = chan + (ok ? ((size_t)gh * WIDTH + gw) : 0);
                const uint32_t dst = s_tile_base
                    + (uint32_t)(((buf * CH + cc) * TILE_FLOATS + r * TSTRIDE + col) * 4);
                cp_async4(dst, src, ok ? 4 : 0);
            }
        }
        cp_async_commit();
    };

    issue_pair(0, 0);

    #pragma unroll 1
    for (int it = 0; it < CHANNELS / CH; it++) {
        const int buf = it & 1;
        const int c0 = it * CH;

        cp_async_wait<0>();   // current pair's data has landed
        __syncthreads();      // visible to all threads; prev buffer fully read

        if (it + 1 < CHANNELS / CH)
            issue_pair(c0 + CH, buf ^ 1);   // overlaps with compute below

        float acc[CH][PX];
        #pragma unroll
        for (int cc = 0; cc < CH; cc++)
            #pragma unroll
            for (int p = 0; p < PX; p++) acc[cc][p] = 0.f;

        #pragma unroll
        for (int i = 0; i < KSZ; i++) {
            #pragma unroll
            for (int cc = 0; cc < CH; cc++) {
                const float* row = &s_tile[buf][cc][(ty + i) * TSTRIDE + PX * tx];
                const float4 a  = *reinterpret_cast<const float4*>(row);
                const float4 bq = *reinterpret_cast<const float4*>(row + 4);
                const float v[8] = {a.x, a.y, a.z, a.w, bq.x, bq.y, bq.z, bq.w};
                #pragma unroll
                for (int p = 0; p < PX; p++)
                    #pragma unroll
                    for (int j = 0; j < KSZ; j++)
                        acc[cc][p] = fmaf(v[p + j], wk[p * 25 + i * KSZ + j], acc[cc][p]);
            }
        }

        #pragma unroll
        for (int cc = 0; cc < CH; cc++) {
            float4 o = {acc[cc][0], acc[cc][1], acc[cc][2], acc[cc][3]};
            *reinterpret_cast<float4*>(
                &outb[((size_t)(c0 + cc) * HEIGHT + h) * WIDTH + wbase]) = o;
        }
    }
}

extern "C" void kernel_launch(void* const* d_in, const int* in_sizes, int n_in,
                              void* d_out, int out_size)
{
    const float* input       = (const float*)d_in[0];
    const float* kernel_bank = (const float*)d_in[1];
    const int*   buckets     = (const int*)d_in[2];
    float*       output      = (float*)d_out;

    dim3 block(BTX, BTY, 1);
    dim3 grid(WIDTH / TILE_OW, HEIGHT / TILE_OH, BATCH);   // (3, 12, 8)
    csconv2d_kernel<<<grid, block>>>(input, kernel_bank, buckets, output);
}